// round 1
// baseline (speedup 1.0000x reference)
#include <cuda_runtime.h>
#include <math.h>

#define NN 10000
#define NE 160000
#define NCH 32

// ---------------- scratch (static device globals; no allocation) ----------------
__device__ float g_U[NE * 3];            // unit vectors per edge
__device__ int   g_cnt[NN];
__device__ int   g_off[NN + 1];
__device__ int   g_cur[NN];
__device__ int   g_elist[NE];
__device__ float g_H0[NN * NCH];         // rank-0 features (N,C)
__device__ float g_H1[NN * NCH * 3];     // rank-1 (N,C,3)
__device__ float g_H2[NN * NCH * 9];     // rank-2 (N,C,9)
__device__ float g_ACC[NE * 96];         // per-edge acc_c (E, 96) : [c*32 + ch]

// ---------------- init: zero features/counters, embed atoms ----------------
__global__ void k_init(const float* __restrict__ emb, const int* __restrict__ atoms) {
    int t = blockIdx.x * 256 + threadIdx.x;
    if (t < NN * NCH * 9) g_H2[t] = 0.f;
    if (t < NN * NCH * 3) g_H1[t] = 0.f;
    if (t < NN * NCH)     g_H0[t] = emb[atoms[t >> 5] * NCH + (t & 31)];
    if (t < NN)           g_cnt[t] = 0;
}

// ---------------- geometry + histogram over dst ----------------
__global__ void k_geom(const float* __restrict__ pos, const int* __restrict__ ei) {
    int e = blockIdx.x * 256 + threadIdx.x;
    if (e >= NE) return;
    int s = ei[e], d = ei[NE + e];
    float rx = pos[d * 3 + 0] - pos[s * 3 + 0];
    float ry = pos[d * 3 + 1] - pos[s * 3 + 1];
    float rz = pos[d * 3 + 2] - pos[s * 3 + 2];
    float nrm = sqrtf(rx * rx + ry * ry + rz * rz);
    float inv = 1.0f / (nrm + 1e-9f);
    g_U[e * 3 + 0] = rx * inv;
    g_U[e * 3 + 1] = ry * inv;
    g_U[e * 3 + 2] = rz * inv;
    atomicAdd(&g_cnt[d], 1);
}

// ---------------- single-block exclusive scan over 10000 counts ----------------
__global__ void k_scan() {
    __shared__ int sh[1024];
    int t = threadIdx.x;
    const int PER = 10;
    int base = t * PER;
    int loc[PER];
    int s = 0;
#pragma unroll
    for (int i = 0; i < PER; i++) {
        int idx = base + i;
        int v = (idx < NN) ? g_cnt[idx] : 0;
        loc[i] = s;
        s += v;
    }
    sh[t] = s;
    __syncthreads();
    for (int off = 1; off < 1024; off <<= 1) {
        int v = (t >= off) ? sh[t - off] : 0;
        __syncthreads();
        sh[t] += v;
        __syncthreads();
    }
    int excl = sh[t] - s;
#pragma unroll
    for (int i = 0; i < PER; i++) {
        int idx = base + i;
        if (idx < NN) g_off[idx] = excl + loc[i];
    }
    if (t == 1023) g_off[NN] = sh[1023];
}

__global__ void k_cur() {
    int i = blockIdx.x * 256 + threadIdx.x;
    if (i < NN) g_cur[i] = g_off[i];
}

__global__ void k_fill(const int* __restrict__ ei) {
    int e = blockIdx.x * 256 + threadIdx.x;
    if (e >= NE) return;
    int d = ei[NE + e];
    int p = atomicAdd(&g_cur[d], 1);
    g_elist[p] = e;
}

// ---------------- edge kernel: fused S-build + (96x96)@(96xE) GEMM ----------------
// block = 256 threads, processes 128 edges; k-dim chunked by rank a (3 chunks of 32)
__global__ __launch_bounds__(256) void k_edge(const int* __restrict__ ei,
                                              const float* __restrict__ W_ab, int l) {
    __shared__ float Wt[32 * 96];        // Wt[j'][k] for current a-chunk
    __shared__ float Ssh[128 * 33];      // Ssh[e_loc][j'] (rowstride 33: conflict-free)
    int tid = threadIdx.x;
    int warp = tid >> 5, lane = tid & 31;
    int mg = tid & 15;       // k-group: thread owns k = mg + 16*kk, kk=0..5
    int ng = tid >> 4;       // e-group: thread owns e_loc = ng + 16*ee, ee=0..7
    int e_base = blockIdx.x * 128;       // NE = 1250*128 exactly, no guards needed

    float acc[6][8];
#pragma unroll
    for (int kk = 0; kk < 6; kk++)
#pragma unroll
        for (int ee = 0; ee < 8; ee++) acc[kk][ee] = 0.f;

#pragma unroll
    for (int a = 0; a < 3; a++) {
        // ---- phase 1: compute s_a for 128 edges (8 warps x 16 edges, lane=channel)
#pragma unroll 4
        for (int t2 = 0; t2 < 16; t2++) {
            int e_loc = warp * 16 + t2;
            int e = e_base + e_loc;
            int src = ei[e];
            float s;
            if (a == 0) {
                s = g_H0[src * 32 + lane];
            } else {
                float u0 = g_U[e * 3 + 0], u1 = g_U[e * 3 + 1], u2 = g_U[e * 3 + 2];
                if (a == 1) {
                    const float* hp = g_H1 + src * 96 + lane * 3;
                    s = hp[0] * u0 + hp[1] * u1 + hp[2] * u2;
                } else {
                    const float* hp = g_H2 + src * 288 + lane * 9;
                    s = (hp[0] * u0 + hp[1] * u1 + hp[2] * u2) * u0
                      + (hp[3] * u0 + hp[4] * u1 + hp[5] * u2) * u1
                      + (hp[6] * u0 + hp[7] * u1 + hp[8] * u2) * u2;
                }
            }
            Ssh[e_loc * 33 + lane] = s;
        }
        // ---- load W chunk: Wt[j'*96 + k] = W_ab[l, k/32, a, k%32, j']
        for (int idx = tid; idx < 32 * 96; idx += 256) {
            int j = idx / 96, k = idx - j * 96;
            Wt[idx] = W_ab[((l * 3 + (k >> 5)) * 3 + a) * 1024 + (k & 31) * 32 + j];
        }
        __syncthreads();
        // ---- GEMM: acc[k][e] += sum_j Wt[j][k] * Ssh[e][j]
#pragma unroll 8
        for (int j = 0; j < 32; j++) {
            float wv[6], sv[8];
#pragma unroll
            for (int kk = 0; kk < 6; kk++) wv[kk] = Wt[j * 96 + mg + 16 * kk];
#pragma unroll
            for (int ee = 0; ee < 8; ee++) sv[ee] = Ssh[(ng + 16 * ee) * 33 + j];
#pragma unroll
            for (int kk = 0; kk < 6; kk++)
#pragma unroll
                for (int ee = 0; ee < 8; ee++) acc[kk][ee] += wv[kk] * sv[ee];
        }
        __syncthreads();
    }
    // ---- store ACC (E,96): per-instr warp writes 2 contiguous 64B chunks
#pragma unroll
    for (int ee = 0; ee < 8; ee++) {
        int e = e_base + ng + 16 * ee;
        float* op = g_ACC + e * 96 + mg;
#pragma unroll
        for (int kk = 0; kk < 6; kk++) op[16 * kk] = acc[kk][ee];
    }
}

// ---------------- node kernel: CSR gather + messages + per-node channel mixing ----
// warp per node, lane = channel
__global__ __launch_bounds__(256) void k_node(const float* __restrict__ ws_w,
                                              const float* __restrict__ cwg,
                                              const float* __restrict__ mwg,
                                              int l, int write_out,
                                              float* __restrict__ out) {
    __shared__ __align__(16) float HS[8][384];   // [warp][j*12 + d]
    __shared__ __align__(16) float MS[8][384];
    int warp = threadIdx.x >> 5, lane = threadIdx.x & 31;
    int node = blockIdx.x * 8 + warp;
    float* hs = HS[warp];
    float* ms = MS[warp];

    // ---- gather A_c(node) from edge accs (atomic-free via CSR)
    float A0 = 0.f, A1[3] = {0.f, 0.f, 0.f};
    float A2[9] = {0.f, 0.f, 0.f, 0.f, 0.f, 0.f, 0.f, 0.f, 0.f};
    int beg = g_off[node], end = g_off[node + 1];
    for (int idx = beg; idx < end; idx++) {
        int e = g_elist[idx];
        float u0 = g_U[e * 3 + 0], u1 = g_U[e * 3 + 1], u2 = g_U[e * 3 + 2];
        const float* ap = g_ACC + e * 96 + lane;
        float a0 = ap[0], a1 = ap[32], a2 = ap[64];
        A0 += a0;
        A1[0] += a1 * u0; A1[1] += a1 * u1; A1[2] += a1 * u2;
        float b0 = a2 * u0, b1 = a2 * u1, b2 = a2 * u2;
        A2[0] += b0 * u0; A2[1] += b0 * u1; A2[2] += b0 * u2;
        A2[3] += b1 * u0; A2[4] += b1 * u1; A2[5] += b1 * u2;
        A2[6] += b2 * u0; A2[7] += b2 * u1; A2[8] += b2 * u2;
    }

    // ---- messages: m_c = (w0 + w1*s0 + w2*s0^2) * A_c   (per channel)
    const float* ws = ws_w + l * 288 + lane;
    float s0 = A0;
    float f0 = ws[0]   + ws[32]  * s0 + ws[64]  * s0 * s0;
    float f1 = ws[96]  + ws[128] * s0 + ws[160] * s0 * s0;
    float f2 = ws[192] + ws[224] * s0 + ws[256] * s0 * s0;
    float M0 = f0 * A0;
    float M1[3], M2[9];
#pragma unroll
    for (int d = 0; d < 3; d++) M1[d] = f1 * A1[d];
#pragma unroll
    for (int d = 0; d < 9; d++) M2[d] = f2 * A2[d];

    size_t nbase = (size_t)l * 3 * NN + node;

    // ---------------- c = 0 ----------------
    {
        const float* cw = cwg + (nbase + 0 * NN) * 1024 + lane * 32;
        const float* mw = mwg + (nbase + 0 * NN) * 1024 + lane * 32;
        float cr[32], mr[32];
#pragma unroll
        for (int q = 0; q < 8; q++) {
            float4 v = ((const float4*)cw)[q];
            cr[4 * q] = v.x; cr[4 * q + 1] = v.y; cr[4 * q + 2] = v.z; cr[4 * q + 3] = v.w;
            float4 w = ((const float4*)mw)[q];
            mr[4 * q] = w.x; mr[4 * q + 1] = w.y; mr[4 * q + 2] = w.z; mr[4 * q + 3] = w.w;
        }
        float h0 = g_H0[node * 32 + lane];
        hs[lane] = h0;
        ms[lane] = M0;
        __syncwarp();
        float o = 0.f;
#pragma unroll
        for (int j = 0; j < 32; j++) o += cr[j] * hs[j] + mr[j] * ms[j];
        __syncwarp();
        if (write_out) out[(node * 32 + lane) * 13 + 0] = o;
        else           g_H0[node * 32 + lane] = o;
    }
    // ---------------- c = 1 ----------------
    {
        const float* cw = cwg + (nbase + 1 * NN) * 1024 + lane * 32;
        const float* mw = mwg + (nbase + 1 * NN) * 1024 + lane * 32;
        float cr[32], mr[32];
#pragma unroll
        for (int q = 0; q < 8; q++) {
            float4 v = ((const float4*)cw)[q];
            cr[4 * q] = v.x; cr[4 * q + 1] = v.y; cr[4 * q + 2] = v.z; cr[4 * q + 3] = v.w;
            float4 w = ((const float4*)mw)[q];
            mr[4 * q] = w.x; mr[4 * q + 1] = w.y; mr[4 * q + 2] = w.z; mr[4 * q + 3] = w.w;
        }
        const float* hp = g_H1 + node * 96 + lane * 3;
        float h0 = hp[0], h1 = hp[1], h2v = hp[2];
        hs[lane * 12 + 0] = h0;  hs[lane * 12 + 1] = h1;  hs[lane * 12 + 2] = h2v;
        ms[lane * 12 + 0] = M1[0]; ms[lane * 12 + 1] = M1[1]; ms[lane * 12 + 2] = M1[2];
        __syncwarp();
        float o0 = 0.f, o1 = 0.f, o2 = 0.f;
#pragma unroll
        for (int j = 0; j < 32; j++) {
            float c_ = cr[j], m_ = mr[j];
            float2 hv = *(const float2*)&hs[j * 12];
            float  hz = hs[j * 12 + 2];
            float2 mv = *(const float2*)&ms[j * 12];
            float  mz = ms[j * 12 + 2];
            o0 += c_ * hv.x + m_ * mv.x;
            o1 += c_ * hv.y + m_ * mv.y;
            o2 += c_ * hz  + m_ * mz;
        }
        __syncwarp();
        if (write_out) {
            out[(node * 32 + lane) * 13 + 1] = o0;
            out[(node * 32 + lane) * 13 + 2] = o1;
            out[(node * 32 + lane) * 13 + 3] = o2;
        } else {
            float* op = g_H1 + node * 96 + lane * 3;
            op[0] = o0; op[1] = o1; op[2] = o2;
        }
    }
    // ---------------- c = 2 ----------------
    {
        const float* cw = cwg + (nbase + 2 * NN) * 1024 + lane * 32;
        const float* mw = mwg + (nbase + 2 * NN) * 1024 + lane * 32;
        float cr[32], mr[32];
#pragma unroll
        for (int q = 0; q < 8; q++) {
            float4 v = ((const float4*)cw)[q];
            cr[4 * q] = v.x; cr[4 * q + 1] = v.y; cr[4 * q + 2] = v.z; cr[4 * q + 3] = v.w;
            float4 w = ((const float4*)mw)[q];
            mr[4 * q] = w.x; mr[4 * q + 1] = w.y; mr[4 * q + 2] = w.z; mr[4 * q + 3] = w.w;
        }
        const float* hp = g_H2 + node * 288 + lane * 9;
        float h[9];
#pragma unroll
        for (int d = 0; d < 9; d++) h[d] = hp[d];
#pragma unroll
        for (int d = 0; d < 9; d++) { hs[lane * 12 + d] = h[d]; ms[lane * 12 + d] = M2[d]; }
        __syncwarp();
        float o[9];
#pragma unroll
        for (int d = 0; d < 9; d++) o[d] = 0.f;
#pragma unroll
        for (int j = 0; j < 32; j++) {
            float c_ = cr[j], m_ = mr[j];
            float4 ha = *(const float4*)&hs[j * 12];
            float4 hb = *(const float4*)&hs[j * 12 + 4];
            float  hc = hs[j * 12 + 8];
            float4 ma = *(const float4*)&ms[j * 12];
            float4 mb = *(const float4*)&ms[j * 12 + 4];
            float  mc = ms[j * 12 + 8];
            o[0] += c_ * ha.x + m_ * ma.x;
            o[1] += c_ * ha.y + m_ * ma.y;
            o[2] += c_ * ha.z + m_ * ma.z;
            o[3] += c_ * ha.w + m_ * ma.w;
            o[4] += c_ * hb.x + m_ * mb.x;
            o[5] += c_ * hb.y + m_ * mb.y;
            o[6] += c_ * hb.z + m_ * mb.z;
            o[7] += c_ * hb.w + m_ * mb.w;
            o[8] += c_ * hc  + m_ * mc;
        }
        __syncwarp();
        if (write_out) {
#pragma unroll
            for (int d = 0; d < 9; d++) out[(node * 32 + lane) * 13 + 4 + d] = o[d];
        } else {
            float* op = g_H2 + node * 288 + lane * 9;
#pragma unroll
            for (int d = 0; d < 9; d++) op[d] = o[d];
        }
    }
}

extern "C" void kernel_launch(void* const* d_in, const int* in_sizes, int n_in,
                              void* d_out, int out_size) {
    (void)in_sizes; (void)n_in; (void)out_size;
    const float* pos   = (const float*)d_in[0];
    const int*   ei    = (const int*)d_in[1];
    const int*   atoms = (const int*)d_in[2];
    const float* emb   = (const float*)d_in[3];
    const float* W_ab  = (const float*)d_in[4];
    const float* ws_w  = (const float*)d_in[5];
    const float* cw    = (const float*)d_in[6];
    const float* mw    = (const float*)d_in[7];
    float* out = (float*)d_out;

    k_init<<<(NN * NCH * 9 + 255) / 256, 256>>>(emb, atoms);
    k_geom<<<(NE + 255) / 256, 256>>>(pos, ei);
    k_scan<<<1, 1024>>>();
    k_cur<<<(NN + 255) / 256, 256>>>();
    k_fill<<<(NE + 255) / 256, 256>>>(ei);

    for (int l = 0; l < 2; l++) {
        k_edge<<<NE / 128, 256>>>(ei, W_ab, l);
        k_node<<<NN / 8, 256>>>(ws_w, cw, mw, l, (l == 1) ? 1 : 0, out);
    }
}

// round 3
// speedup vs baseline: 1.5833x; 1.5833x over previous
#include <cuda_runtime.h>
#include <math.h>

#define NN 10000
#define NE 160000
#define NCH 32

// ---------------- scratch (static device globals; no allocation) ----------------
__device__ float g_U[NE * 3];            // unit vectors per edge
__device__ int   g_cnt[NN];
__device__ int   g_off[NN + 1];
__device__ int   g_cur[NN];
__device__ int   g_elist[NE];
__device__ float g_H0[NN * NCH];         // rank-0 features (N,C)
__device__ float g_H1[NN * NCH * 3];     // rank-1 (N,C,3)
__device__ float g_H2[NN * NCH * 9];     // rank-2 (N,C,9)
__device__ float g_ACC[NE * 96];         // per-edge acc_c (E, 96) : [c*32 + ch]
__device__ float g_accvec[96];           // layer-0 constant acc vector (c*32+j)

// ---------------- packed f32x2 helpers ----------------
__device__ __forceinline__ unsigned long long pack2(float x, float y) {
    unsigned long long r; asm("mov.b64 %0, {%1,%2};" : "=l"(r) : "f"(x), "f"(y)); return r;
}
__device__ __forceinline__ void unpack2(unsigned long long v, float& x, float& y) {
    asm("mov.b64 {%0,%1}, %2;" : "=f"(x), "=f"(y) : "l"(v));
}
__device__ __forceinline__ unsigned long long fma2(unsigned long long a, unsigned long long b,
                                                   unsigned long long c) {
    unsigned long long d;
    asm("fma.rn.f32x2 %0, %1, %2, %3;" : "=l"(d) : "l"(a), "l"(b), "l"(c));
    return d;
}

// ---------------- init: embed atoms, zero counters, layer-0 accvec ----------------
__global__ void k_init(const float* __restrict__ emb, const int* __restrict__ atoms,
                       const float* __restrict__ W_ab) {
    int t = blockIdx.x * 256 + threadIdx.x;
    if (t < NN * NCH) g_H0[t] = emb[atoms[t >> 5] * NCH + (t & 31)];
    if (t < NN)       g_cnt[t] = 0;
    if (t < 96) {
        // accvec[c*32+j] = sum_k W_ab[0, c, 0, j, k] * emb[k]
        int c = t >> 5, j = t & 31;
        const float* wp = W_ab + (c * 3) * 1024 + j * 32;
        float s = 0.f;
#pragma unroll
        for (int k = 0; k < 32; k++) s += wp[k] * emb[k];
        g_accvec[t] = s;
    }
}

// ---------------- geometry + histogram over dst ----------------
__global__ void k_geom(const float* __restrict__ pos, const int* __restrict__ ei) {
    int e = blockIdx.x * 256 + threadIdx.x;
    if (e >= NE) return;
    int s = ei[e], d = ei[NE + e];
    float rx = pos[d * 3 + 0] - pos[s * 3 + 0];
    float ry = pos[d * 3 + 1] - pos[s * 3 + 1];
    float rz = pos[d * 3 + 2] - pos[s * 3 + 2];
    float nrm = sqrtf(rx * rx + ry * ry + rz * rz);
    float inv = 1.0f / (nrm + 1e-9f);
    g_U[e * 3 + 0] = rx * inv;
    g_U[e * 3 + 1] = ry * inv;
    g_U[e * 3 + 2] = rz * inv;
    atomicAdd(&g_cnt[d], 1);
}

// ---------------- single-block exclusive scan over 10000 counts ----------------
__global__ void k_scan() {
    __shared__ int sh[1024];
    int t = threadIdx.x;
    const int PER = 10;
    int base = t * PER;
    int loc[PER];
    int s = 0;
#pragma unroll
    for (int i = 0; i < PER; i++) {
        int idx = base + i;
        int v = (idx < NN) ? g_cnt[idx] : 0;
        loc[i] = s;
        s += v;
    }
    sh[t] = s;
    __syncthreads();
    for (int off = 1; off < 1024; off <<= 1) {
        int v = (t >= off) ? sh[t - off] : 0;
        __syncthreads();
        sh[t] += v;
        __syncthreads();
    }
    int excl = sh[t] - s;
#pragma unroll
    for (int i = 0; i < PER; i++) {
        int idx = base + i;
        if (idx < NN) { g_off[idx] = excl + loc[i]; g_cur[idx] = excl + loc[i]; }
    }
    if (t == 1023) g_off[NN] = sh[1023];
}

__global__ void k_fill(const int* __restrict__ ei) {
    int e = blockIdx.x * 256 + threadIdx.x;
    if (e >= NE) return;
    int d = ei[NE + e];
    int p = atomicAdd(&g_cur[d], 1);
    g_elist[p] = e;
}

// ---------------- layer-0 node kernel ----------------
// Exploits: h0 constant across nodes, h1=h2=0  =>  A_c(i) = accvec_c (outer) S_c(i)
// where S = segment-sums of (1, u, u (outer) u). One warp per node, lane = channel.
__global__ __launch_bounds__(256) void k_node0(const float* __restrict__ ws_w,
                                               const float* __restrict__ cwg,
                                               const float* __restrict__ mwg) {
    __shared__ float HS[8][32];
    __shared__ __align__(16) float MS[8][384];
    int warp = threadIdx.x >> 5, lane = threadIdx.x & 31;
    int node = blockIdx.x * 8 + warp;
    float* ms = MS[warp];
    int beg = g_off[node], end = g_off[node + 1];

    // geometric moments over incident edges (lanes strided, then butterfly reduce)
    float su0 = 0, su1 = 0, su2 = 0;
    float s00 = 0, s01 = 0, s02 = 0, s11 = 0, s12 = 0, s22 = 0;
    for (int idx = beg + lane; idx < end; idx += 32) {
        int e = g_elist[idx];
        float u0 = g_U[e * 3 + 0], u1 = g_U[e * 3 + 1], u2 = g_U[e * 3 + 2];
        su0 += u0; su1 += u1; su2 += u2;
        s00 += u0 * u0; s01 += u0 * u1; s02 += u0 * u2;
        s11 += u1 * u1; s12 += u1 * u2; s22 += u2 * u2;
    }
#pragma unroll
    for (int off = 16; off; off >>= 1) {
        su0 += __shfl_xor_sync(~0u, su0, off);
        su1 += __shfl_xor_sync(~0u, su1, off);
        su2 += __shfl_xor_sync(~0u, su2, off);
        s00 += __shfl_xor_sync(~0u, s00, off);
        s01 += __shfl_xor_sync(~0u, s01, off);
        s02 += __shfl_xor_sync(~0u, s02, off);
        s11 += __shfl_xor_sync(~0u, s11, off);
        s12 += __shfl_xor_sync(~0u, s12, off);
        s22 += __shfl_xor_sync(~0u, s22, off);
    }
    float S0 = (float)(end - beg);
    float av0 = g_accvec[lane], av1 = g_accvec[32 + lane], av2 = g_accvec[64 + lane];
    float A0 = av0 * S0;
    float A1[3] = {av1 * su0, av1 * su1, av1 * su2};
    float A2[9] = {av2 * s00, av2 * s01, av2 * s02,
                   av2 * s01, av2 * s11, av2 * s12,
                   av2 * s02, av2 * s12, av2 * s22};

    // messages: m_c = (w0 + w1*s0 + w2*s0^2) * A_c  (s0 = A0, per channel), l=0
    const float* ws = ws_w + lane;
    float s0 = A0;
    float f0 = ws[0]   + ws[32]  * s0 + ws[64]  * s0 * s0;
    float f1 = ws[96]  + ws[128] * s0 + ws[160] * s0 * s0;
    float f2 = ws[192] + ws[224] * s0 + ws[256] * s0 * s0;
    float M0 = f0 * A0;
    float M1[3], M2[9];
#pragma unroll
    for (int d = 0; d < 3; d++) M1[d] = f1 * A1[d];
#pragma unroll
    for (int d = 0; d < 9; d++) M2[d] = f2 * A2[d];

    size_t nbase = (size_t)node;   // l=0

    // ---- c = 0: o = channel_w @ h0 + message_w @ M0
    {
        const float* cw = cwg + nbase * 1024 + lane * 32;
        const float* mw = mwg + nbase * 1024 + lane * 32;
        float cr[32], mr[32];
#pragma unroll
        for (int q = 0; q < 8; q++) {
            float4 v = ((const float4*)cw)[q];
            cr[4 * q] = v.x; cr[4 * q + 1] = v.y; cr[4 * q + 2] = v.z; cr[4 * q + 3] = v.w;
            float4 w = ((const float4*)mw)[q];
            mr[4 * q] = w.x; mr[4 * q + 1] = w.y; mr[4 * q + 2] = w.z; mr[4 * q + 3] = w.w;
        }
        float h0 = g_H0[node * 32 + lane];
        HS[warp][lane] = h0;
        ms[lane] = M0;
        __syncwarp();
        float o = 0.f;
#pragma unroll
        for (int j = 0; j < 32; j++) o += cr[j] * HS[warp][j] + mr[j] * ms[j];
        __syncwarp();
        g_H0[node * 32 + lane] = o;
    }
    // ---- c = 1: o = message_w @ M1  (h1 == 0)
    {
        const float* mw = mwg + (nbase + NN) * 1024 + lane * 32;
        float mr[32];
#pragma unroll
        for (int q = 0; q < 8; q++) {
            float4 w = ((const float4*)mw)[q];
            mr[4 * q] = w.x; mr[4 * q + 1] = w.y; mr[4 * q + 2] = w.z; mr[4 * q + 3] = w.w;
        }
        ms[lane * 4 + 0] = M1[0]; ms[lane * 4 + 1] = M1[1]; ms[lane * 4 + 2] = M1[2];
        __syncwarp();
        float o0 = 0.f, o1 = 0.f, o2 = 0.f;
#pragma unroll
        for (int j = 0; j < 32; j++) {
            float m_ = mr[j];
            float2 mv = *(const float2*)&ms[j * 4];
            float  mz = ms[j * 4 + 2];
            o0 += m_ * mv.x; o1 += m_ * mv.y; o2 += m_ * mz;
        }
        __syncwarp();
        float* op = g_H1 + node * 96 + lane * 3;
        op[0] = o0; op[1] = o1; op[2] = o2;
    }
    // ---- c = 2: o = message_w @ M2  (h2 == 0)
    {
        const float* mw = mwg + (nbase + 2 * NN) * 1024 + lane * 32;
        float mr[32];
#pragma unroll
        for (int q = 0; q < 8; q++) {
            float4 w = ((const float4*)mw)[q];
            mr[4 * q] = w.x; mr[4 * q + 1] = w.y; mr[4 * q + 2] = w.z; mr[4 * q + 3] = w.w;
        }
#pragma unroll
        for (int d = 0; d < 9; d++) ms[lane * 12 + d] = M2[d];
        __syncwarp();
        float o[9];
#pragma unroll
        for (int d = 0; d < 9; d++) o[d] = 0.f;
#pragma unroll
        for (int j = 0; j < 32; j++) {
            float m_ = mr[j];
            float4 ma = *(const float4*)&ms[j * 12];
            float4 mb = *(const float4*)&ms[j * 12 + 4];
            float  mc = ms[j * 12 + 8];
            o[0] += m_ * ma.x; o[1] += m_ * ma.y; o[2] += m_ * ma.z; o[3] += m_ * ma.w;
            o[4] += m_ * mb.x; o[5] += m_ * mb.y; o[6] += m_ * mb.z; o[7] += m_ * mb.w;
            o[8] += m_ * mc;
        }
        __syncwarp();
        float* op = g_H2 + node * 288 + lane * 9;
#pragma unroll
        for (int d = 0; d < 9; d++) op[d] = o[d];
    }
}

// ---------------- layer-1 edge kernel: fused S-build + (96x96)@(96xE) GEMM -------
// block = 256 threads, 128 edges; k chunked by rank a; packed f32x2 FMA.
// Thread tile: k = mg + 16*kk (kk 0..5), e = ng + 16*ee (ee 0..7).
// WtP layout: WtP[j*96 + mg*6 + kk] = W[l=1, c(k), a, ch(k), j] with k = mg+16*kk,
// so the (kk, kk+1) pair is one aligned LDS.64 and lanes are conflict-free.
__global__ __launch_bounds__(256) void k_edge(const int* __restrict__ ei,
                                              const float* __restrict__ W_ab) {
    __shared__ __align__(8) float WtP[32 * 96];
    __shared__ float Ssh[128 * 33];
    int tid = threadIdx.x;
    int warp = tid >> 5, lane = tid & 31;
    int mg = tid & 15;
    int ng = tid >> 4;
    int e_base = blockIdx.x * 128;

    unsigned long long acc2[3][8];
#pragma unroll
    for (int p = 0; p < 3; p++)
#pragma unroll
        for (int ee = 0; ee < 8; ee++) acc2[p][ee] = 0ull;

#pragma unroll
    for (int a = 0; a < 3; a++) {
        // ---- phase 1: s_a for 128 edges (8 warps x 16 edges, lane = channel)
#pragma unroll 4
        for (int t2 = 0; t2 < 16; t2++) {
            int e_loc = warp * 16 + t2;
            int e = e_base + e_loc;
            int src = ei[e];
            float s;
            if (a == 0) {
                s = g_H0[src * 32 + lane];
            } else {
                float u0 = g_U[e * 3 + 0], u1 = g_U[e * 3 + 1], u2 = g_U[e * 3 + 2];
                if (a == 1) {
                    const float* hp = g_H1 + src * 96 + lane * 3;
                    s = hp[0] * u0 + hp[1] * u1 + hp[2] * u2;
                } else {
                    const float* hp = g_H2 + src * 288 + lane * 9;
                    s = (hp[0] * u0 + hp[1] * u1 + hp[2] * u2) * u0
                      + (hp[3] * u0 + hp[4] * u1 + hp[5] * u2) * u1
                      + (hp[6] * u0 + hp[7] * u1 + hp[8] * u2) * u2;
                }
            }
            Ssh[e_loc * 33 + lane] = s;
        }
        // ---- load W chunk (l=1), permuted for paired access
        for (int idx = tid; idx < 32 * 96; idx += 256) {
            int j = idx / 96, r = idx - j * 96;
            int mgi = r / 6, kki = r - mgi * 6;
            int k = mgi + 16 * kki;
            WtP[idx] = W_ab[((3 + (k >> 5)) * 3 + a) * 1024 + (k & 31) * 32 + j];
        }
        __syncthreads();
        // ---- GEMM: acc[k][e] += sum_j W[j][k] * S[e][j]  (packed over k-pairs)
#pragma unroll 8
        for (int j = 0; j < 32; j++) {
            const unsigned long long* wp =
                (const unsigned long long*)&WtP[j * 96 + mg * 6];
            unsigned long long w0 = wp[0], w1 = wp[1], w2 = wp[2];
            unsigned long long s2[8];
#pragma unroll
            for (int ee = 0; ee < 8; ee++) {
                float s = Ssh[(ng + 16 * ee) * 33 + j];
                s2[ee] = pack2(s, s);
            }
#pragma unroll
            for (int ee = 0; ee < 8; ee++) {
                acc2[0][ee] = fma2(w0, s2[ee], acc2[0][ee]);
                acc2[1][ee] = fma2(w1, s2[ee], acc2[1][ee]);
                acc2[2][ee] = fma2(w2, s2[ee], acc2[2][ee]);
            }
        }
        __syncthreads();
    }
    // ---- store ACC (E,96): per-instr half-warp writes a contiguous 64B chunk
#pragma unroll
    for (int ee = 0; ee < 8; ee++) {
        int e = e_base + ng + 16 * ee;
        float* op = g_ACC + e * 96 + mg;
#pragma unroll
        for (int p = 0; p < 3; p++) {
            float lo, hi;
            unpack2(acc2[p][ee], lo, hi);
            op[16 * (2 * p)]     = lo;
            op[16 * (2 * p + 1)] = hi;
        }
    }
}

// ---------------- layer-1 node kernel: CSR gather + messages + update -> out ----
__global__ __launch_bounds__(256) void k_node1(const float* __restrict__ ws_w,
                                               const float* __restrict__ cwg,
                                               const float* __restrict__ mwg,
                                               float* __restrict__ out) {
    __shared__ __align__(16) float HS[8][384];
    __shared__ __align__(16) float MS[8][384];
    int warp = threadIdx.x >> 5, lane = threadIdx.x & 31;
    int node = blockIdx.x * 8 + warp;
    float* hs = HS[warp];
    float* ms = MS[warp];

    float A0 = 0.f, A1[3] = {0.f, 0.f, 0.f};
    float A2[9] = {0.f, 0.f, 0.f, 0.f, 0.f, 0.f, 0.f, 0.f, 0.f};
    int beg = g_off[node], end = g_off[node + 1];
    for (int idx = beg; idx < end; idx++) {
        int e = g_elist[idx];
        float u0 = g_U[e * 3 + 0], u1 = g_U[e * 3 + 1], u2 = g_U[e * 3 + 2];
        const float* ap = g_ACC + e * 96 + lane;
        float a0 = ap[0], a1 = ap[32], a2 = ap[64];
        A0 += a0;
        A1[0] += a1 * u0; A1[1] += a1 * u1; A1[2] += a1 * u2;
        float b0 = a2 * u0, b1 = a2 * u1, b2 = a2 * u2;
        A2[0] += b0 * u0; A2[1] += b0 * u1; A2[2] += b0 * u2;
        A2[3] += b1 * u0; A2[4] += b1 * u1; A2[5] += b1 * u2;
        A2[6] += b2 * u0; A2[7] += b2 * u1; A2[8] += b2 * u2;
    }

    const float* ws = ws_w + 288 + lane;   // l=1
    float s0 = A0;
    float f0 = ws[0]   + ws[32]  * s0 + ws[64]  * s0 * s0;
    float f1 = ws[96]  + ws[128] * s0 + ws[160] * s0 * s0;
    float f2 = ws[192] + ws[224] * s0 + ws[256] * s0 * s0;
    float M0 = f0 * A0;
    float M1[3], M2[9];
#pragma unroll
    for (int d = 0; d < 3; d++) M1[d] = f1 * A1[d];
#pragma unroll
    for (int d = 0; d < 9; d++) M2[d] = f2 * A2[d];

    size_t nbase = (size_t)3 * NN + node;  // l=1

    // ---- c = 0
    {
        const float* cw = cwg + nbase * 1024 + lane * 32;
        const float* mw = mwg + nbase * 1024 + lane * 32;
        float cr[32], mr[32];
#pragma unroll
        for (int q = 0; q < 8; q++) {
            float4 v = ((const float4*)cw)[q];
            cr[4 * q] = v.x; cr[4 * q + 1] = v.y; cr[4 * q + 2] = v.z; cr[4 * q + 3] = v.w;
            float4 w = ((const float4*)mw)[q];
            mr[4 * q] = w.x; mr[4 * q + 1] = w.y; mr[4 * q + 2] = w.z; mr[4 * q + 3] = w.w;
        }
        float h0 = g_H0[node * 32 + lane];
        hs[lane] = h0;
        ms[lane] = M0;
        __syncwarp();
        float o = 0.f;
#pragma unroll
        for (int j = 0; j < 32; j++) o += cr[j] * hs[j] + mr[j] * ms[j];
        __syncwarp();
        out[(node * 32 + lane) * 13 + 0] = o;
    }
    // ---- c = 1
    {
        const float* cw = cwg + (nbase + NN) * 1024 + lane * 32;
        const float* mw = mwg + (nbase + NN) * 1024 + lane * 32;
        float cr[32], mr[32];
#pragma unroll
        for (int q = 0; q < 8; q++) {
            float4 v = ((const float4*)cw)[q];
            cr[4 * q] = v.x; cr[4 * q + 1] = v.y; cr[4 * q + 2] = v.z; cr[4 * q + 3] = v.w;
            float4 w = ((const float4*)mw)[q];
            mr[4 * q] = w.x; mr[4 * q + 1] = w.y; mr[4 * q + 2] = w.z; mr[4 * q + 3] = w.w;
        }
        const float* hp = g_H1 + node * 96 + lane * 3;
        hs[lane * 12 + 0] = hp[0]; hs[lane * 12 + 1] = hp[1]; hs[lane * 12 + 2] = hp[2];
        ms[lane * 12 + 0] = M1[0]; ms[lane * 12 + 1] = M1[1]; ms[lane * 12 + 2] = M1[2];
        __syncwarp();
        float o0 = 0.f, o1 = 0.f, o2 = 0.f;
#pragma unroll
        for (int j = 0; j < 32; j++) {
            float c_ = cr[j], m_ = mr[j];
            float2 hv = *(const float2*)&hs[j * 12];
            float  hz = hs[j * 12 + 2];
            float2 mv = *(const float2*)&ms[j * 12];
            float  mz = ms[j * 12 + 2];
            o0 += c_ * hv.x + m_ * mv.x;
            o1 += c_ * hv.y + m_ * mv.y;
            o2 += c_ * hz  + m_ * mz;
        }
        __syncwarp();
        out[(node * 32 + lane) * 13 + 1] = o0;
        out[(node * 32 + lane) * 13 + 2] = o1;
        out[(node * 32 + lane) * 13 + 3] = o2;
    }
    // ---- c = 2
    {
        const float* cw = cwg + (nbase + 2 * NN) * 1024 + lane * 32;
        const float* mw = mwg + (nbase + 2 * NN) * 1024 + lane * 32;
        float cr[32], mr[32];
#pragma unroll
        for (int q = 0; q < 8; q++) {
            float4 v = ((const float4*)cw)[q];
            cr[4 * q] = v.x; cr[4 * q + 1] = v.y; cr[4 * q + 2] = v.z; cr[4 * q + 3] = v.w;
            float4 w = ((const float4*)mw)[q];
            mr[4 * q] = w.x; mr[4 * q + 1] = w.y; mr[4 * q + 2] = w.z; mr[4 * q + 3] = w.w;
        }
        const float* hp = g_H2 + node * 288 + lane * 9;
#pragma unroll
        for (int d = 0; d < 9; d++) { hs[lane * 12 + d] = hp[d]; ms[lane * 12 + d] = M2[d]; }
        __syncwarp();
        float o[9];
#pragma unroll
        for (int d = 0; d < 9; d++) o[d] = 0.f;
#pragma unroll
        for (int j = 0; j < 32; j++) {
            float c_ = cr[j], m_ = mr[j];
            float4 ha = *(const float4*)&hs[j * 12];
            float4 hb = *(const float4*)&hs[j * 12 + 4];
            float  hc = hs[j * 12 + 8];
            float4 ma = *(const float4*)&ms[j * 12];
            float4 mb = *(const float4*)&ms[j * 12 + 4];
            float  mc = ms[j * 12 + 8];
            o[0] += c_ * ha.x + m_ * ma.x;
            o[1] += c_ * ha.y + m_ * ma.y;
            o[2] += c_ * ha.z + m_ * ma.z;
            o[3] += c_ * ha.w + m_ * ma.w;
            o[4] += c_ * hb.x + m_ * mb.x;
            o[5] += c_ * hb.y + m_ * mb.y;
            o[6] += c_ * hb.z + m_ * mb.z;
            o[7] += c_ * hb.w + m_ * mb.w;
            o[8] += c_ * hc  + m_ * mc;
        }
        __syncwarp();
#pragma unroll
        for (int d = 0; d < 9; d++) out[(node * 32 + lane) * 13 + 4 + d] = o[d];
    }
}

extern "C" void kernel_launch(void* const* d_in, const int* in_sizes, int n_in,
                              void* d_out, int out_size) {
    (void)in_sizes; (void)n_in; (void)out_size;
    const float* pos   = (const float*)d_in[0];
    const int*   ei    = (const int*)d_in[1];
    const int*   atoms = (const int*)d_in[2];
    const float* emb   = (const float*)d_in[3];
    const float* W_ab  = (const float*)d_in[4];
    const float* ws_w  = (const float*)d_in[5];
    const float* cw    = (const float*)d_in[6];
    const float* mw    = (const float*)d_in[7];
    float* out = (float*)d_out;

    k_init<<<(NN * NCH + 255) / 256, 256>>>(emb, atoms, W_ab);
    k_geom<<<(NE + 255) / 256, 256>>>(pos, ei);
    k_scan<<<1, 1024>>>();
    k_fill<<<(NE + 255) / 256, 256>>>(ei);

    // layer 0: edge phase collapses to geometric moments (h0 const, h1=h2=0)
    k_node0<<<NN / 8, 256>>>(ws_w, cw, mw);
    // layer 1: full pipeline
    k_edge<<<NE / 128, 256>>>(ei, W_ab);
    k_node1<<<NN / 8, 256>>>(ws_w, cw, mw, out);
}

// round 4
// speedup vs baseline: 1.7753x; 1.1213x over previous
#include <cuda_runtime.h>
#include <math.h>

#define NN 10000
#define NE 160000

// ---------------- scratch (static device globals; no allocation) ----------------
__device__ float g_US[NE * 4];           // sorted unit vectors (float4 per edge slot)
__device__ int   g_srcs[NE];             // sorted src node per CSR slot
__device__ int   g_cnt[NN];
__device__ int   g_off[NN + 1];
__device__ int   g_cur[NN];
__device__ float g_H0[NN * 32];          // (N,C)
__device__ float g_H1[NN * 96];          // (N, d-major: d*32 + ch)
__device__ float g_H2[NN * 288];         // (N, d-major: d*32 + ch)
__device__ float g_ACC[NE * 96];         // per-CSR-slot acc (k = c*32 + ch)
__device__ float g_accvec[96];           // layer-0 constant acc vector
__device__ float g_M[NN * 416];          // messages: [0,32)=M0; [32,128)=M1 d-major; [128,416)=M2 d-major

// ---------------- packed f32x2 helpers ----------------
__device__ __forceinline__ unsigned long long pack2(float x, float y) {
    unsigned long long r; asm("mov.b64 %0, {%1,%2};" : "=l"(r) : "f"(x), "f"(y)); return r;
}
__device__ __forceinline__ void unpack2(unsigned long long v, float& x, float& y) {
    asm("mov.b64 {%0,%1}, %2;" : "=f"(x), "=f"(y) : "l"(v));
}
__device__ __forceinline__ unsigned long long fma2(unsigned long long a, unsigned long long b,
                                                   unsigned long long c) {
    unsigned long long d;
    asm("fma.rn.f32x2 %0, %1, %2, %3;" : "=l"(d) : "l"(a), "l"(b), "l"(c));
    return d;
}

// ---------------- init: embed atoms, zero counters, layer-0 accvec ----------------
__global__ void k_init(const float* __restrict__ emb, const int* __restrict__ atoms,
                       const float* __restrict__ W_ab) {
    int t = blockIdx.x * 256 + threadIdx.x;
    if (t < NN * 32) g_H0[t] = emb[atoms[t >> 5] * 32 + (t & 31)];
    if (t < NN)      g_cnt[t] = 0;
    if (t < 96) {
        int c = t >> 5, j = t & 31;
        const float* wp = W_ab + (c * 3) * 1024 + j * 32;
        float s = 0.f;
#pragma unroll
        for (int k = 0; k < 32; k++) s += wp[k] * emb[k];
        g_accvec[t] = s;
    }
}

// ---------------- histogram over dst ----------------
__global__ void k_hist(const int* __restrict__ ei) {
    int e = blockIdx.x * 256 + threadIdx.x;
    if (e < NE) atomicAdd(&g_cnt[ei[NE + e]], 1);
}

// ---------------- single-block exclusive scan ----------------
__global__ void k_scan() {
    __shared__ int sh[1024];
    int t = threadIdx.x;
    const int PER = 10;
    int base = t * PER;
    int loc[PER];
    int s = 0;
#pragma unroll
    for (int i = 0; i < PER; i++) {
        int idx = base + i;
        int v = (idx < NN) ? g_cnt[idx] : 0;
        loc[i] = s;
        s += v;
    }
    sh[t] = s;
    __syncthreads();
    for (int off = 1; off < 1024; off <<= 1) {
        int v = (t >= off) ? sh[t - off] : 0;
        __syncthreads();
        sh[t] += v;
        __syncthreads();
    }
    int excl = sh[t] - s;
#pragma unroll
    for (int i = 0; i < PER; i++) {
        int idx = base + i;
        if (idx < NN) { g_off[idx] = excl + loc[i]; g_cur[idx] = excl + loc[i]; }
    }
    if (t == 1023) g_off[NN] = sh[1023];
}

// ---------------- geometry + scatter into CSR order ----------------
__global__ void k_fill(const int* __restrict__ ei, const float* __restrict__ pos) {
    int e = blockIdx.x * 256 + threadIdx.x;
    if (e >= NE) return;
    int s = ei[e], d = ei[NE + e];
    float rx = pos[d * 3 + 0] - pos[s * 3 + 0];
    float ry = pos[d * 3 + 1] - pos[s * 3 + 1];
    float rz = pos[d * 3 + 2] - pos[s * 3 + 2];
    float nrm = sqrtf(rx * rx + ry * ry + rz * rz);
    float inv = 1.0f / (nrm + 1e-9f);
    int p = atomicAdd(&g_cur[d], 1);
    g_srcs[p] = s;
    ((float4*)g_US)[p] = make_float4(rx * inv, ry * inv, rz * inv, 0.f);
}

// ---------------- layer-0 gather: geometric moments -> messages ----------------
// h0 const across nodes, h1=h2=0  =>  A_c(i) = accvec_c (outer) moments_c(i)
__global__ __launch_bounds__(256) void k_gather0(const float* __restrict__ ws_w) {
    int warp = threadIdx.x >> 5, lane = threadIdx.x & 31;
    int node = blockIdx.x * 8 + warp;
    int beg = g_off[node], end = g_off[node + 1];

    float su0 = 0, su1 = 0, su2 = 0;
    float s00 = 0, s01 = 0, s02 = 0, s11 = 0, s12 = 0, s22 = 0;
    for (int idx = beg + lane; idx < end; idx += 32) {
        float4 u = ((const float4*)g_US)[idx];
        su0 += u.x; su1 += u.y; su2 += u.z;
        s00 += u.x * u.x; s01 += u.x * u.y; s02 += u.x * u.z;
        s11 += u.y * u.y; s12 += u.y * u.z; s22 += u.z * u.z;
    }
#pragma unroll
    for (int off = 16; off; off >>= 1) {
        su0 += __shfl_xor_sync(~0u, su0, off);
        su1 += __shfl_xor_sync(~0u, su1, off);
        su2 += __shfl_xor_sync(~0u, su2, off);
        s00 += __shfl_xor_sync(~0u, s00, off);
        s01 += __shfl_xor_sync(~0u, s01, off);
        s02 += __shfl_xor_sync(~0u, s02, off);
        s11 += __shfl_xor_sync(~0u, s11, off);
        s12 += __shfl_xor_sync(~0u, s12, off);
        s22 += __shfl_xor_sync(~0u, s22, off);
    }
    float S0 = (float)(end - beg);
    float av0 = g_accvec[lane], av1 = g_accvec[32 + lane], av2 = g_accvec[64 + lane];
    float A0 = av0 * S0;
    float A1[3] = {av1 * su0, av1 * su1, av1 * su2};
    float A2[9] = {av2 * s00, av2 * s01, av2 * s02,
                   av2 * s01, av2 * s11, av2 * s12,
                   av2 * s02, av2 * s12, av2 * s22};

    const float* ws = ws_w + lane;  // l=0
    float s0 = A0;
    float f0 = ws[0]   + ws[32]  * s0 + ws[64]  * s0 * s0;
    float f1 = ws[96]  + ws[128] * s0 + ws[160] * s0 * s0;
    float f2 = ws[192] + ws[224] * s0 + ws[256] * s0 * s0;

    float* Mp = g_M + node * 416;
    Mp[lane] = f0 * A0;
#pragma unroll
    for (int d = 0; d < 3; d++) Mp[32 + d * 32 + lane] = f1 * A1[d];
#pragma unroll
    for (int d = 0; d < 9; d++) Mp[128 + d * 32 + lane] = f2 * A2[d];
}

// ---------------- layer-1 gather: stream sorted ACC/U -> messages ----------------
__global__ __launch_bounds__(256) void k_gather1(const float* __restrict__ ws_w) {
    int warp = threadIdx.x >> 5, lane = threadIdx.x & 31;
    int node = blockIdx.x * 8 + warp;
    int beg = g_off[node], end = g_off[node + 1];

    float A0 = 0.f, A1[3] = {0.f, 0.f, 0.f};
    float A2[9] = {0.f, 0.f, 0.f, 0.f, 0.f, 0.f, 0.f, 0.f, 0.f};
    for (int idx = beg; idx < end; idx++) {
        float4 u = ((const float4*)g_US)[idx];
        const float* ap = g_ACC + (size_t)idx * 96 + lane;
        float a0 = ap[0], a1 = ap[32], a2 = ap[64];
        A0 += a0;
        A1[0] += a1 * u.x; A1[1] += a1 * u.y; A1[2] += a1 * u.z;
        float b0 = a2 * u.x, b1 = a2 * u.y, b2 = a2 * u.z;
        A2[0] += b0 * u.x; A2[1] += b0 * u.y; A2[2] += b0 * u.z;
        A2[3] += b1 * u.x; A2[4] += b1 * u.y; A2[5] += b1 * u.z;
        A2[6] += b2 * u.x; A2[7] += b2 * u.y; A2[8] += b2 * u.z;
    }

    const float* ws = ws_w + 288 + lane;  // l=1
    float s0 = A0;
    float f0 = ws[0]   + ws[32]  * s0 + ws[64]  * s0 * s0;
    float f1 = ws[96]  + ws[128] * s0 + ws[160] * s0 * s0;
    float f2 = ws[192] + ws[224] * s0 + ws[256] * s0 * s0;

    float* Mp = g_M + node * 416;
    Mp[lane] = f0 * A0;
#pragma unroll
    for (int d = 0; d < 3; d++) Mp[32 + d * 32 + lane] = f1 * A1[d];
#pragma unroll
    for (int d = 0; d < 9; d++) Mp[128 + d * 32 + lane] = f2 * A2[d];
}

// ---------------- update: warp per (node, c); pure weight streaming ----------------
// l==0: h1=h2=0 -> c>0 skips channel_w; writes H. l==1: full; writes out.
__global__ __launch_bounds__(256) void k_update(const float* __restrict__ cwg,
                                                const float* __restrict__ mwg,
                                                int l, float* __restrict__ out) {
    __shared__ float XS[8][288];
    __shared__ float HS[8][288];
    int warp = threadIdx.x >> 5, lane = threadIdx.x & 31;
    int wg = blockIdx.x * 8 + warp;          // 0..29999
    int c = wg / NN;
    int node = wg - c * NN;
    float* xs = XS[warp];
    float* hs = HS[warp];
    const float* Mp = g_M + node * 416;
    size_t wbase = (((size_t)l * 3 + c) * NN + node) * 1024 + (size_t)lane * 32;
    bool use_cw = (l == 1) || (c == 0);

    float mr[32], cr[32];
#pragma unroll
    for (int q = 0; q < 8; q++) {
        float4 w = ((const float4*)(mwg + wbase))[q];
        mr[4 * q] = w.x; mr[4 * q + 1] = w.y; mr[4 * q + 2] = w.z; mr[4 * q + 3] = w.w;
    }
    if (use_cw) {
#pragma unroll
        for (int q = 0; q < 8; q++) {
            float4 v = ((const float4*)(cwg + wbase))[q];
            cr[4 * q] = v.x; cr[4 * q + 1] = v.y; cr[4 * q + 2] = v.z; cr[4 * q + 3] = v.w;
        }
    }

    if (c == 0) {
        xs[lane] = Mp[lane];
        hs[lane] = g_H0[node * 32 + lane];
        __syncwarp();
        float o = 0.f;
#pragma unroll
        for (int j = 0; j < 32; j++) o += cr[j] * hs[j] + mr[j] * xs[j];
        __syncwarp();
        if (l == 0) g_H0[node * 32 + lane] = o;
        else        out[(node * 32 + lane) * 13 + 0] = o;
    } else if (c == 1) {
#pragma unroll
        for (int q = 0; q < 3; q++) xs[q * 32 + lane] = Mp[32 + q * 32 + lane];
        if (use_cw) {
            const float* hp = g_H1 + node * 96;
#pragma unroll
            for (int q = 0; q < 3; q++) hs[q * 32 + lane] = hp[q * 32 + lane];
        }
        __syncwarp();
        float o0 = 0.f, o1 = 0.f, o2 = 0.f;
        if (use_cw) {
#pragma unroll
            for (int j = 0; j < 32; j++) {
                float w2 = mr[j], w1 = cr[j];
                o0 += w1 * hs[j]      + w2 * xs[j];
                o1 += w1 * hs[32 + j] + w2 * xs[32 + j];
                o2 += w1 * hs[64 + j] + w2 * xs[64 + j];
            }
        } else {
#pragma unroll
            for (int j = 0; j < 32; j++) {
                float w2 = mr[j];
                o0 += w2 * xs[j]; o1 += w2 * xs[32 + j]; o2 += w2 * xs[64 + j];
            }
        }
        __syncwarp();
        if (l == 0) {
            float* op = g_H1 + node * 96;
            op[lane] = o0; op[32 + lane] = o1; op[64 + lane] = o2;
        } else {
            float* op = out + (node * 32 + lane) * 13 + 1;
            op[0] = o0; op[1] = o1; op[2] = o2;
        }
    } else {
#pragma unroll
        for (int q = 0; q < 9; q++) xs[q * 32 + lane] = Mp[128 + q * 32 + lane];
        if (use_cw) {
            const float* hp = g_H2 + node * 288;
#pragma unroll
            for (int q = 0; q < 9; q++) hs[q * 32 + lane] = hp[q * 32 + lane];
        }
        __syncwarp();
        float o[9];
#pragma unroll
        for (int d = 0; d < 9; d++) o[d] = 0.f;
        if (use_cw) {
#pragma unroll
            for (int j = 0; j < 32; j++) {
                float w2 = mr[j], w1 = cr[j];
#pragma unroll
                for (int d = 0; d < 9; d++) o[d] += w1 * hs[d * 32 + j] + w2 * xs[d * 32 + j];
            }
        } else {
#pragma unroll
            for (int j = 0; j < 32; j++) {
                float w2 = mr[j];
#pragma unroll
                for (int d = 0; d < 9; d++) o[d] += w2 * xs[d * 32 + j];
            }
        }
        __syncwarp();
        if (l == 0) {
            float* op = g_H2 + node * 288;
#pragma unroll
            for (int d = 0; d < 9; d++) op[d * 32 + lane] = o[d];
        } else {
            float* op = out + (node * 32 + lane) * 13 + 4;
#pragma unroll
            for (int d = 0; d < 9; d++) op[d] = o[d];
        }
    }
}

// ---------------- layer-1 edge kernel: fused S-build + (96x96)@(96xE) GEMM -------
// 256 threads / 128 CSR slots; all of W (3 chunks) resident; single __syncthreads.
// Dynamic smem: W 9216 floats + S 3*128*32 floats = 86016 B.
__global__ __launch_bounds__(256) void k_edge(const float* __restrict__ W_ab) {
    extern __shared__ float sm[];
    float* Wt = sm;            // [a*3072 + j*96 + mg*6 + kk]
    float* Ss = sm + 9216;     // [a*4096 + e_loc*32 + lane]
    int tid = threadIdx.x;
    int warp = tid >> 5, lane = tid & 31;
    int mg = tid & 15;
    int ng = tid >> 4;
    int e_base = blockIdx.x * 128;

    // ---- phase 1: s_a for all 3 ranks, one pass (8 warps x 16 slots, lane=channel)
#pragma unroll 4
    for (int t2 = 0; t2 < 16; t2++) {
        int e_loc = warp * 16 + t2;
        int idx = e_base + e_loc;
        int src = g_srcs[idx];
        float4 u = ((const float4*)g_US)[idx];
        float s0 = g_H0[src * 32 + lane];
        const float* h1 = g_H1 + src * 96;
        float s1 = h1[lane] * u.x + h1[32 + lane] * u.y + h1[64 + lane] * u.z;
        const float* h2 = g_H2 + src * 288;
        float s2 = u.x * (h2[lane] * u.x + h2[32 + lane] * u.y + h2[64 + lane] * u.z)
                 + u.y * (h2[96 + lane] * u.x + h2[128 + lane] * u.y + h2[160 + lane] * u.z)
                 + u.z * (h2[192 + lane] * u.x + h2[224 + lane] * u.y + h2[256 + lane] * u.z);
        Ss[e_loc * 32 + lane] = s0;
        Ss[4096 + e_loc * 32 + lane] = s1;
        Ss[8192 + e_loc * 32 + lane] = s2;
    }
    // ---- load all W (l=1), permuted for paired LDS.64 access
    for (int t = tid; t < 9216; t += 256) {
        int a = t / 3072, rem = t - a * 3072;
        int j = rem / 96, r = rem - j * 96;
        int mgi = r / 6, kki = r - mgi * 6;
        int k = mgi + 16 * kki;
        Wt[t] = W_ab[((3 + (k >> 5)) * 3 + a) * 1024 + (k & 31) * 32 + j];
    }
    __syncthreads();

    unsigned long long acc2[3][8];
#pragma unroll
    for (int p = 0; p < 3; p++)
#pragma unroll
        for (int ee = 0; ee < 8; ee++) acc2[p][ee] = 0ull;

#pragma unroll
    for (int a = 0; a < 3; a++) {
        const float* Wa = Wt + a * 3072;
        const float* Sa = Ss + a * 4096;
#pragma unroll 8
        for (int j = 0; j < 32; j++) {
            const unsigned long long* wp = (const unsigned long long*)&Wa[j * 96 + mg * 6];
            unsigned long long w0 = wp[0], w1 = wp[1], w2 = wp[2];
            unsigned long long s2[8];
#pragma unroll
            for (int ee = 0; ee < 8; ee++) {
                float s = Sa[(ng + 16 * ee) * 32 + j];
                s2[ee] = pack2(s, s);
            }
#pragma unroll
            for (int ee = 0; ee < 8; ee++) {
                acc2[0][ee] = fma2(w0, s2[ee], acc2[0][ee]);
                acc2[1][ee] = fma2(w1, s2[ee], acc2[1][ee]);
                acc2[2][ee] = fma2(w2, s2[ee], acc2[2][ee]);
            }
        }
    }
    // ---- store ACC at CSR position (streaming for gather1)
#pragma unroll
    for (int ee = 0; ee < 8; ee++) {
        int idx = e_base + ng + 16 * ee;
        float* op = g_ACC + (size_t)idx * 96 + mg;
#pragma unroll
        for (int p = 0; p < 3; p++) {
            float lo, hi;
            unpack2(acc2[p][ee], lo, hi);
            op[16 * (2 * p)]     = lo;
            op[16 * (2 * p + 1)] = hi;
        }
    }
}

extern "C" void kernel_launch(void* const* d_in, const int* in_sizes, int n_in,
                              void* d_out, int out_size) {
    (void)in_sizes; (void)n_in; (void)out_size;
    const float* pos   = (const float*)d_in[0];
    const int*   ei    = (const int*)d_in[1];
    const int*   atoms = (const int*)d_in[2];
    const float* emb   = (const float*)d_in[3];
    const float* W_ab  = (const float*)d_in[4];
    const float* ws_w  = (const float*)d_in[5];
    const float* cw    = (const float*)d_in[6];
    const float* mw    = (const float*)d_in[7];
    float* out = (float*)d_out;

    const int EDGE_SMEM = (9216 + 12288) * 4;   // 86016 B
    cudaFuncSetAttribute(k_edge, cudaFuncAttributeMaxDynamicSharedMemorySize, EDGE_SMEM);

    k_init<<<1250, 256>>>(emb, atoms, W_ab);
    k_hist<<<625, 256>>>(ei);
    k_scan<<<1, 1024>>>();
    k_fill<<<625, 256>>>(ei, pos);

    // layer 0 (edge phase analytic)
    k_gather0<<<NN / 8, 256>>>(ws_w);
    k_update<<<3 * NN / 8, 256>>>(cw, mw, 0, out);
    // layer 1
    k_edge<<<NE / 128, 256, EDGE_SMEM>>>(W_ab);
    k_gather1<<<NN / 8, 256>>>(ws_w);
    k_update<<<3 * NN / 8, 256>>>(cw, mw, 1, out);
}